// round 15
// baseline (speedup 1.0000x reference)
#include <cuda_runtime.h>
#include <cuda_fp16.h>

#define N 192
#define NV (N / 4)          // 48 quads per x-row
#define NNN (N * N * N)
#define STEPS 20

// c field ping-pong as unorm16 (c is clipped to [0,1] every step).
__device__ ushort4 g_c16a[NNN / 4];
__device__ ushort4 g_c16b[NNN / 4];
// Interleaved fp16 maps premultiplied by delta_t: {D0..D3, R0..R3} per quad.
__device__ uint4 g_DR[NNN / 4];

// ---- prepass: (D, rho) fp32 -> interleaved fp16 * delta_t ----
__global__ __launch_bounds__(256) void convert_maps_kernel(
    const float4* __restrict__ D4, const float4* __restrict__ R4,
    const float* __restrict__ dt_ptr, uint4* __restrict__ DR)
{
    const int i = blockIdx.x * blockDim.x + threadIdx.x;
    if (i >= NNN / 4) return;
    const float dt = dt_ptr[0] * (1.0f / (float)STEPS);
    const float4 d = D4[i];
    const float4 r = R4[i];
    uint4 o;
    *(__half2*)&o.x = __floats2half2_rn(d.x * dt, d.y * dt);
    *(__half2*)&o.y = __floats2half2_rn(d.z * dt, d.w * dt);
    *(__half2*)&o.z = __floats2half2_rn(r.x * dt, r.y * dt);
    *(__half2*)&o.w = __floats2half2_rn(r.z * dt, r.w * dt);
    DR[i] = o;
}

__device__ __forceinline__ float  u2f(unsigned short u) {
    return (float)u * (1.0f / 65535.0f);
}
__device__ __forceinline__ float4 uq2f(ushort4 u) {
    return make_float4(u2f(u.x), u2f(u.y), u2f(u.z), u2f(u.w));
}
__device__ __forceinline__ unsigned short f2u(float f) {   // f already in [0,1]
    return (unsigned short)__float2uint_rn(f * 65535.0f);
}

// out = saturate(c + D'*lap + R'*(c - c^2)); D'/R' pre-scaled by dt.
__device__ __forceinline__ float upd(float c, float xl, float xr,
                                     float ym, float yp, float zm, float zp,
                                     float D, float R)
{
    float lap = fmaf(-6.f, c, (xl + xr) + (ym + yp) + (zm + zp));
    return __saturatef(fmaf(D, lap, fmaf(R, fmaf(-c, c, c), c)));
}

__device__ __forceinline__ float4 quad_upd(float4 c, float xl, float xr,
                                           float4 ym, float4 yp,
                                           float4 zm, float4 zp, uint4 dr)
{
    const float2 d01 = __half22float2(*(const __half2*)&dr.x);
    const float2 d23 = __half22float2(*(const __half2*)&dr.y);
    const float2 r01 = __half22float2(*(const __half2*)&dr.z);
    const float2 r23 = __half22float2(*(const __half2*)&dr.w);
    float4 o;
    o.x = upd(c.x, xl,  c.y, ym.x, yp.x, zm.x, zp.x, d01.x, r01.x);
    o.y = upd(c.y, c.x, c.z, ym.y, yp.y, zm.y, zp.y, d01.y, r01.y);
    o.z = upd(c.z, c.y, c.w, ym.z, yp.z, zm.z, zp.z, d23.x, r23.x);
    o.w = upd(c.w, c.z, xr,  ym.w, yp.w, zm.w, zp.w, d23.y, r23.y);
    return o;
}

// Each thread computes two quads stacked in y (rows y0, y0+1).
// SRC16/DST16 select unorm16 vs fp32 for the c field.
template <bool SRC16, bool DST16>
__global__ __launch_bounds__(192) void rd_step_kernel(
    const void* __restrict__ srcv,
    void* __restrict__ dstv,
    const uint4* __restrict__ DR)
{
    const int tx = threadIdx.x;                                  // 0..47
    const int y0 = (blockIdx.y * blockDim.y + threadIdx.y) * 2;  // even
    const int z  = blockIdx.z;
    const int idxA = (z * N + y0) * NV + tx;
    const int idxB = idxA + NV;

    const float4 zero = make_float4(0.f, 0.f, 0.f, 0.f);

    float4 cA, cB, ym, yp, zmA, zmB, zpA, zpB;
    float lA, rA, lB, rB;

    if (SRC16) {
        const ushort4* s4 = (const ushort4*)srcv;
        const unsigned short* s = (const unsigned short*)srcv;
        cA = uq2f(s4[idxA]);
        cB = uq2f(s4[idxB]);
        ym  = (y0 > 0)     ? uq2f(s4[idxA - NV])     : zero;
        yp  = (y0 < N - 2) ? uq2f(s4[idxB + NV])     : zero;
        zmA = (z > 0)      ? uq2f(s4[idxA - NV * N]) : zero;
        zmB = (z > 0)      ? uq2f(s4[idxB - NV * N]) : zero;
        zpA = (z < N - 1)  ? uq2f(s4[idxA + NV * N]) : zero;
        zpB = (z < N - 1)  ? uq2f(s4[idxB + NV * N]) : zero;
        lA = (tx > 0)      ? u2f(s[idxA * 4 - 1]) : 0.f;
        rA = (tx < NV - 1) ? u2f(s[idxA * 4 + 4]) : 0.f;
        lB = (tx > 0)      ? u2f(s[idxB * 4 - 1]) : 0.f;
        rB = (tx < NV - 1) ? u2f(s[idxB * 4 + 4]) : 0.f;
    } else {
        const float4* s4 = (const float4*)srcv;
        const float* s = (const float*)srcv;
        cA = s4[idxA];
        cB = s4[idxB];
        ym  = (y0 > 0)     ? s4[idxA - NV]     : zero;
        yp  = (y0 < N - 2) ? s4[idxB + NV]     : zero;
        zmA = (z > 0)      ? s4[idxA - NV * N] : zero;
        zmB = (z > 0)      ? s4[idxB - NV * N] : zero;
        zpA = (z < N - 1)  ? s4[idxA + NV * N] : zero;
        zpB = (z < N - 1)  ? s4[idxB + NV * N] : zero;
        lA = (tx > 0)      ? s[idxA * 4 - 1] : 0.f;
        rA = (tx < NV - 1) ? s[idxA * 4 + 4] : 0.f;
        lB = (tx > 0)      ? s[idxB * 4 - 1] : 0.f;
        rB = (tx < NV - 1) ? s[idxB * 4 + 4] : 0.f;
    }

    const uint4 drA = DR[idxA];
    const uint4 drB = DR[idxB];

    // Row A: down-neighbor ym, up-neighbor cB. Row B: down cA, up yp.
    const float4 oA = quad_upd(cA, lA, rA, ym, cB, zmA, zpA, drA);
    const float4 oB = quad_upd(cB, lB, rB, cA, yp, zmB, zpB, drB);

    if (DST16) {
        ushort4* d4 = (ushort4*)dstv;
        d4[idxA] = make_ushort4(f2u(oA.x), f2u(oA.y), f2u(oA.z), f2u(oA.w));
        d4[idxB] = make_ushort4(f2u(oB.x), f2u(oB.y), f2u(oB.z), f2u(oB.w));
    } else {
        float4* d4 = (float4*)dstv;
        d4[idxA] = oA;
        d4[idxB] = oB;
    }
}

extern "C" void kernel_launch(void* const* d_in, const int* in_sizes, int n_in,
                              void* d_out, int out_size)
{
    const float4* c_init = (const float4*)d_in[0];
    const float4* D_map  = (const float4*)d_in[1];
    const float4* rho    = (const float4*)d_in[2];
    const float*  dt     = (const float*)d_in[3];

    ushort4 *A = nullptr, *B = nullptr;
    uint4* DR = nullptr;
    cudaGetSymbolAddress((void**)&A, g_c16a);
    cudaGetSymbolAddress((void**)&B, g_c16b);
    cudaGetSymbolAddress((void**)&DR, g_DR);

    convert_maps_kernel<<<(NNN / 4 + 255) / 256, 256>>>(D_map, rho, dt, DR);

    dim3 block(NV, 4, 1);       // 48 x 4 = 192 threads, 8 y-rows per block
    dim3 grid(1, N / 8, N);     // (1, 24, 192)

    // step 0: fp32 -> u16 (A). steps 1..18: u16 ping-pong (odd: A->B).
    // step 19: u16 -> fp32 d_out. Data after step 18 is in A.
    rd_step_kernel<false, true><<<grid, block>>>(c_init, A, DR);
    for (int i = 1; i <= 18; ++i) {
        if (i & 1) rd_step_kernel<true, true><<<grid, block>>>(A, B, DR);
        else       rd_step_kernel<true, true><<<grid, block>>>(B, A, DR);
    }
    rd_step_kernel<true, false><<<grid, block>>>(A, d_out, DR);
}

// round 17
// speedup vs baseline: 1.3779x; 1.3779x over previous
#include <cuda_runtime.h>
#include <cuda_fp16.h>

#define N 192
#define NO (N / 8)          // 24 octs per x-row
#define NNN (N * N * N)
#define STEPS 20
#define INV65535 (1.0f / 65535.0f)

// c field ping-pong as unorm16 (c is clipped to [0,1] every step).
__device__ uint4 g_c16a[NNN / 8];
__device__ uint4 g_c16b[NNN / 8];
// Interleaved fp16 maps premultiplied by delta_t: {D0..D3, R0..R3} per quad.
__device__ uint4 g_DR[NNN / 4];

// ---- prepass 1: (D, rho) fp32 -> interleaved fp16 * delta_t ----
__global__ __launch_bounds__(256) void convert_maps_kernel(
    const float4* __restrict__ D4, const float4* __restrict__ R4,
    const float* __restrict__ dt_ptr, uint4* __restrict__ DR)
{
    const int i = blockIdx.x * blockDim.x + threadIdx.x;
    if (i >= NNN / 4) return;
    const float dt = dt_ptr[0] * (1.0f / (float)STEPS);
    const float4 d = D4[i];
    const float4 r = R4[i];
    uint4 o;
    *(__half2*)&o.x = __floats2half2_rn(d.x * dt, d.y * dt);
    *(__half2*)&o.y = __floats2half2_rn(d.z * dt, d.w * dt);
    *(__half2*)&o.z = __floats2half2_rn(r.x * dt, r.y * dt);
    *(__half2*)&o.w = __floats2half2_rn(r.z * dt, r.w * dt);
    DR[i] = o;
}

__device__ __forceinline__ unsigned f2u16(float f) {      // f in [0,1]
    return __float2uint_rn(f * 65535.0f);
}

// ---- prepass 2: c_init fp32 -> unorm16 ----
__global__ __launch_bounds__(256) void convert_c_kernel(
    const float4* __restrict__ c4, uint4* __restrict__ c16)
{
    const int i = blockIdx.x * blockDim.x + threadIdx.x;  // one uint4 = 2 float4
    if (i >= NNN / 8) return;
    const float4 a = c4[2 * i];
    const float4 b = c4[2 * i + 1];
    uint4 o;
    o.x = f2u16(__saturatef(a.x)) | (f2u16(__saturatef(a.y)) << 16);
    o.y = f2u16(__saturatef(a.z)) | (f2u16(__saturatef(a.w)) << 16);
    o.z = f2u16(__saturatef(b.x)) | (f2u16(__saturatef(b.y)) << 16);
    o.w = f2u16(__saturatef(b.z)) | (f2u16(__saturatef(b.w)) << 16);
    c16[i] = o;
}

__device__ __forceinline__ void ext8(uint4 q, int e[8]) {
    e[0] = (int)(q.x & 0xFFFFu); e[1] = (int)(q.x >> 16);
    e[2] = (int)(q.y & 0xFFFFu); e[3] = (int)(q.y >> 16);
    e[4] = (int)(q.z & 0xFFFFu); e[5] = (int)(q.z >> 16);
    e[6] = (int)(q.w & 0xFFFFu); e[7] = (int)(q.w >> 16);
}

// Each thread handles 8 x-elements (one uint4 of u16). Laplacian computed
// exactly in integer domain; 2 I2F per element.
template <bool LAST>
__global__ __launch_bounds__(192) void rd_step16(
    const unsigned short* __restrict__ src,
    void* __restrict__ dstv,
    const uint4* __restrict__ DR)
{
    const int tx = threadIdx.x;                         // 0..23 (oct)
    const int y  = blockIdx.y * blockDim.y + threadIdx.y;
    const int z  = blockIdx.z;
    const int io = (z * N + y) * NO + tx;

    const uint4* s4 = (const uint4*)src;
    const uint4 zq = make_uint4(0u, 0u, 0u, 0u);

    // Wide loads, front-batched.
    const uint4 qc  = s4[io];
    const uint4 qym = (y > 0)     ? s4[io - NO]     : zq;
    const uint4 qyp = (y < N - 1) ? s4[io + NO]     : zq;
    const uint4 qzm = (z > 0)     ? s4[io - NO * N] : zq;
    const uint4 qzp = (z < N - 1) ? s4[io + NO * N] : zq;
    const uint4 dr0 = DR[2 * io];
    const uint4 dr1 = DR[2 * io + 1];
    const int xl = (tx > 0)      ? (int)src[io * 8 - 1] : 0;
    const int xr = (tx < NO - 1) ? (int)src[io * 8 + 8] : 0;

    int ec[8], eym[8], eyp[8], ezm[8], ezp[8];
    ext8(qc, ec); ext8(qym, eym); ext8(qyp, eyp);
    ext8(qzm, ezm); ext8(qzp, ezp);

    float D[8], R[8];
    {
        float2 t;
        t = __half22float2(*(const __half2*)&dr0.x); D[0] = t.x; D[1] = t.y;
        t = __half22float2(*(const __half2*)&dr0.y); D[2] = t.x; D[3] = t.y;
        t = __half22float2(*(const __half2*)&dr0.z); R[0] = t.x; R[1] = t.y;
        t = __half22float2(*(const __half2*)&dr0.w); R[2] = t.x; R[3] = t.y;
        t = __half22float2(*(const __half2*)&dr1.x); D[4] = t.x; D[5] = t.y;
        t = __half22float2(*(const __half2*)&dr1.y); D[6] = t.x; D[7] = t.y;
        t = __half22float2(*(const __half2*)&dr1.z); R[4] = t.x; R[5] = t.y;
        t = __half22float2(*(const __half2*)&dr1.w); R[6] = t.x; R[7] = t.y;
    }

    float o[8];
#pragma unroll
    for (int i = 0; i < 8; ++i) {
        const int xli = (i == 0) ? xl : ec[i - 1];
        const int xri = (i == 7) ? xr : ec[i + 1];
        const int lap = xli + xri + eym[i] + eyp[i] + ezm[i] + ezp[i] - 6 * ec[i];
        const float cf = (float)ec[i] * INV65535;
        const float lf = (float)lap * INV65535;
        // out = saturate(cf + D'*lap + R'*(cf - cf^2))
        o[i] = __saturatef(fmaf(D[i], lf, fmaf(R[i], fmaf(-cf, cf, cf), cf)));
    }

    if (LAST) {
        float4* d = (float4*)dstv;
        d[2 * io]     = make_float4(o[0], o[1], o[2], o[3]);
        d[2 * io + 1] = make_float4(o[4], o[5], o[6], o[7]);
    } else {
        uint4 q;
        q.x = f2u16(o[0]) | (f2u16(o[1]) << 16);
        q.y = f2u16(o[2]) | (f2u16(o[3]) << 16);
        q.z = f2u16(o[4]) | (f2u16(o[5]) << 16);
        q.w = f2u16(o[6]) | (f2u16(o[7]) << 16);
        ((uint4*)dstv)[io] = q;
    }
}

extern "C" void kernel_launch(void* const* d_in, const int* in_sizes, int n_in,
                              void* d_out, int out_size)
{
    const float4* c_init = (const float4*)d_in[0];
    const float4* D_map  = (const float4*)d_in[1];
    const float4* rho    = (const float4*)d_in[2];
    const float*  dt     = (const float*)d_in[3];

    uint4 *A = nullptr, *B = nullptr, *DR = nullptr;
    cudaGetSymbolAddress((void**)&A, g_c16a);
    cudaGetSymbolAddress((void**)&B, g_c16b);
    cudaGetSymbolAddress((void**)&DR, g_DR);

    convert_maps_kernel<<<(NNN / 4 + 255) / 256, 256>>>(D_map, rho, dt, DR);
    convert_c_kernel<<<(NNN / 8 + 255) / 256, 256>>>(c_init, A);

    dim3 block(NO, 8, 1);       // 24 x 8 = 192 threads
    dim3 grid(1, N / 8, N);     // (1, 24, 192)

    // 19 u16->u16 steps (i=0..18: A->B, B->A, ... i even: A->B; ends in B),
    // then final step u16 -> fp32 d_out. Total 20 steps.
    for (int i = 0; i < 19; ++i) {
        const unsigned short* s = (const unsigned short*)((i & 1) ? B : A);
        uint4* dq = (i & 1) ? A : B;
        rd_step16<false><<<grid, block>>>(s, dq, DR);
    }
    rd_step16<true><<<grid, block>>>((const unsigned short*)B, d_out, DR);
}